// round 1
// baseline (speedup 1.0000x reference)
#include <cuda_runtime.h>
#include <cuda_bf16.h>

#define HID 32
#define CUTOFF_SQ 6.25f
#define THREADS 256

__global__ void init_out_kernel(float* out) {
    out[0] = 0.0f;
}

__global__ __launch_bounds__(THREADS)
void pair_energy_kernel(const float* __restrict__ xyz,
                        const float* __restrict__ cell_diag,
                        const float* __restrict__ W1,
                        const float* __restrict__ b1,
                        const float* __restrict__ W2,
                        const float* __restrict__ b2,
                        float* __restrict__ out,
                        int n) {
    __shared__ float w1s[HID];
    __shared__ float b1s[HID];
    __shared__ float w2s[HID];
    __shared__ float b2s;
    __shared__ float cellL[3];
    __shared__ float warp_sums[THREADS / 32];

    int tid = threadIdx.x;
    if (tid < HID) {
        w1s[tid] = W1[tid];
        b1s[tid] = b1[tid];
        w2s[tid] = W2[tid];
    }
    if (tid == 0) b2s = b2[0];
    if (tid < 3) cellL[tid] = cell_diag[tid];
    __syncthreads();

    int i = blockIdx.x;

    float xi = xyz[3 * i + 0];
    float yi = xyz[3 * i + 1];
    float zi = xyz[3 * i + 2];

    float Lx = cellL[0], Ly = cellL[1], Lz = cellL[2];
    float hx = 0.5f * Lx, hy = 0.5f * Ly, hz = 0.5f * Lz;

    float acc = 0.0f;

    for (int j = i + 1 + tid; j < n; j += THREADS) {
        // d[i][j] = xyz[j] - xyz[i]   (reference convention)
        float dx = xyz[3 * j + 0] - xi;
        float dy = xyz[3 * j + 1] - yi;
        float dz = xyz[3 * j + 2] - zi;

        // minimum image exactly as reference: offset from ORIGINAL d
        if (dx >= hx) dx -= Lx; else if (dx < -hx) dx += Lx;
        if (dy >= hy) dy -= Ly; else if (dy < -hy) dy += Ly;
        if (dz >= hz) dz -= Lz; else if (dz < -hz) dz += Lz;

        float r2 = dx * dx + dy * dy + dz * dz;

        if (r2 < CUTOFF_SQ && r2 > 0.0f) {
            float r = sqrtf(r2);
            float e = b2s;
            #pragma unroll
            for (int h = 0; h < HID; h++) {
                e = fmaf(w2s[h], tanhf(fmaf(r, w1s[h], b1s[h])), e);
            }
            acc += e;
        }
    }

    // warp reduction
    #pragma unroll
    for (int off = 16; off > 0; off >>= 1)
        acc += __shfl_down_sync(0xFFFFFFFFu, acc, off);

    int lane = tid & 31;
    int wid = tid >> 5;
    if (lane == 0) warp_sums[wid] = acc;
    __syncthreads();

    if (wid == 0) {
        float v = (lane < THREADS / 32) ? warp_sums[lane] : 0.0f;
        #pragma unroll
        for (int off = 16; off > 0; off >>= 1)
            v += __shfl_down_sync(0xFFFFFFFFu, v, off);
        if (lane == 0 && v != 0.0f) {
            atomicAdd(out, v);
        }
    }
}

extern "C" void kernel_launch(void* const* d_in, const int* in_sizes, int n_in,
                              void* d_out, int out_size) {
    const float* xyz       = (const float*)d_in[0];
    const float* cell_diag = (const float*)d_in[1];
    const float* W1        = (const float*)d_in[2];
    const float* b1        = (const float*)d_in[3];
    const float* W2        = (const float*)d_in[4];
    const float* b2        = (const float*)d_in[5];
    float* out = (float*)d_out;

    int n = in_sizes[0] / 3;  // xyz has n*3 elements

    init_out_kernel<<<1, 1>>>(out);
    pair_energy_kernel<<<n, THREADS>>>(xyz, cell_diag, W1, b1, W2, b2, out, n);
}

// round 2
// speedup vs baseline: 3.2400x; 3.2400x over previous
#include <cuda_runtime.h>
#include <cuda_bf16.h>

#define HID 32
#define CUTOFF 2.5f
#define CUTOFF_SQ 6.25f
#define THREADS 256
#define TBL 4096        // table intervals; TBL+1 entries
#define NMAX 4096

__device__ float g_tbl[TBL + 1];
__device__ float g_x[NMAX];
__device__ float g_y[NMAX];
__device__ float g_z[NMAX];

// Setup: zero output, build SoA coords, build energy table e(r) with exact tanhf.
__global__ void setup_kernel(const float* __restrict__ xyz,
                             const float* __restrict__ W1,
                             const float* __restrict__ b1,
                             const float* __restrict__ W2,
                             const float* __restrict__ b2,
                             float* __restrict__ out,
                             int n) {
    int tid = blockIdx.x * blockDim.x + threadIdx.x;
    if (tid == 0) out[0] = 0.0f;

    if (tid < n) {
        g_x[tid] = xyz[3 * tid + 0];
        g_y[tid] = xyz[3 * tid + 1];
        g_z[tid] = xyz[3 * tid + 2];
    }

    if (tid <= TBL) {
        float r = (CUTOFF / (float)TBL) * (float)tid;
        float e = b2[0];
        #pragma unroll
        for (int h = 0; h < HID; h++) {
            e = fmaf(W2[h], tanhf(fmaf(r, W1[h], b1[h])), e);
        }
        g_tbl[tid] = e;
    }
}

// Each block handles two rows: i0 = blockIdx.x and i1 = n-1-blockIdx.x,
// balancing the triangular pair distribution (each block ~n candidate pairs).
__global__ __launch_bounds__(THREADS)
void pair_energy_kernel(const float* __restrict__ cell_diag,
                        float* __restrict__ out,
                        int n) {
    __shared__ float warp_sums[THREADS / 32];

    const int tid = threadIdx.x;

    const float Lx = cell_diag[0], Ly = cell_diag[1], Lz = cell_diag[2];
    const float hx = 0.5f * Lx, hy = 0.5f * Ly, hz = 0.5f * Lz;
    const float invDr = (float)TBL / CUTOFF;

    float acc = 0.0f;

    #pragma unroll
    for (int half = 0; half < 2; half++) {
        int i = half ? (n - 1 - blockIdx.x) : blockIdx.x;
        // avoid double-processing the middle row when n is odd
        if (half && i == (int)blockIdx.x) break;

        const float xi = g_x[i];
        const float yi = g_y[i];
        const float zi = g_z[i];

        for (int j = i + 1 + tid; j < n; j += THREADS) {
            float dx = g_x[j] - xi;
            float dy = g_y[j] - yi;
            float dz = g_z[j] - zi;

            // minimum image, matching reference (offset computed from raw d)
            dx += (dx < -hx ? Lx : 0.0f) - (dx >= hx ? Lx : 0.0f);
            dy += (dy < -hy ? Ly : 0.0f) - (dy >= hy ? Ly : 0.0f);
            dz += (dz < -hz ? Lz : 0.0f) - (dz >= hz ? Lz : 0.0f);

            float r2 = fmaf(dx, dx, fmaf(dy, dy, dz * dz));

            if (r2 < CUTOFF_SQ && r2 > 0.0f) {
                float r = sqrtf(r2);
                float t = r * invDr;
                int k = (int)t;
                float f = t - (float)k;
                float e0 = g_tbl[k];
                float e1 = g_tbl[k + 1];
                acc += fmaf(f, e1 - e0, e0);
            }
        }
    }

    // warp reduction
    #pragma unroll
    for (int off = 16; off > 0; off >>= 1)
        acc += __shfl_down_sync(0xFFFFFFFFu, acc, off);

    int lane = tid & 31;
    int wid = tid >> 5;
    if (lane == 0) warp_sums[wid] = acc;
    __syncthreads();

    if (wid == 0) {
        float v = (lane < THREADS / 32) ? warp_sums[lane] : 0.0f;
        #pragma unroll
        for (int off = 16; off > 0; off >>= 1)
            v += __shfl_down_sync(0xFFFFFFFFu, v, off);
        if (lane == 0) {
            atomicAdd(out, v);
        }
    }
}

extern "C" void kernel_launch(void* const* d_in, const int* in_sizes, int n_in,
                              void* d_out, int out_size) {
    const float* xyz       = (const float*)d_in[0];
    const float* cell_diag = (const float*)d_in[1];
    const float* W1        = (const float*)d_in[2];
    const float* b1        = (const float*)d_in[3];
    const float* W2        = (const float*)d_in[4];
    const float* b2        = (const float*)d_in[5];
    float* out = (float*)d_out;

    int n = in_sizes[0] / 3;

    int setup_threads = (TBL + 1 > n) ? (TBL + 1) : n;
    setup_kernel<<<(setup_threads + 255) / 256, 256>>>(xyz, W1, b1, W2, b2, out, n);

    int nblocks = (n + 1) / 2;   // paired rows
    pair_energy_kernel<<<nblocks, THREADS>>>(cell_diag, out, n);
}